// round 9
// baseline (speedup 1.0000x reference)
#include <cuda_runtime.h>
#include <cstdint>
#include <cstddef>

// Problem shapes (fixed)
#define Tt   512
#define Bb   16
#define Dd   512
#define Hh   1024
#define G2   2048            // 2*H
#define NB   128             // persistent worker blocks
#define JPB  8               // h columns per block (Hh / NB)
#define STR  1028            // smem row stride in floats (padded)
#define RQS  272             // red per-q2 stride (floats)
#define LN_EPS 1e-5f

typedef unsigned long long u64;

__device__ __forceinline__ void fma2(u64& d, u64 a, u64 b) {
    asm("fma.rn.f32x2 %0, %1, %2, %0;" : "+l"(d) : "l"(a), "l"(b));
}
__device__ __forceinline__ void red_rel_add(unsigned* p, unsigned v) {
    asm volatile("red.release.gpu.global.add.u32 [%0], %1;" :: "l"(p), "r"(v) : "memory");
}
__device__ __forceinline__ unsigned ld_acq(unsigned* p) {
    unsigned v;
    asm volatile("ld.acquire.gpu.global.u32 %0, [%1];" : "=r"(v) : "l"(p) : "memory");
    return v;
}
__device__ __forceinline__ float lo_f(u64 v) { return __uint_as_float((unsigned)v); }
__device__ __forceinline__ float hi_f(u64 v) { return __uint_as_float((unsigned)(v >> 32)); }

// ---------------- device scratch (allocation-free) ----------------
__device__ float    g_w[(size_t)Bb * Tt * G2];   // 64 MB: LN'd projection
__device__ float    g_hbuf[2][Bb * Hh];          // double-buffered hidden state
__device__ unsigned g_counts[8];                 // split barrier counters

// ---------------- init: reset barrier state + h0 ----------------
__global__ void init_state_k(const float* __restrict__ h0) {
    int i = blockIdx.x * blockDim.x + threadIdx.x;
    if (i < Bb * Hh) g_hbuf[0][i] = h0[i & (Hh - 1)];   // broadcast h0 over batch
    if (i < 8)       g_counts[i] = 0u;
}

// ---------------- phase 1: g_w = x @ W^T  (f32x2 tiled GEMM) ----------------
__global__ void __launch_bounds__(256) gemm_xw_k(const float* __restrict__ X,
                                                 const float* __restrict__ W) {
    __shared__ float2 As2[4][128];
    __shared__ float2 Bs2[4][66];

    int tid = threadIdx.x;
    int bx = blockIdx.x;          // n tile (32)
    int by = blockIdx.y;          // m tile (64)
    int tx = tid & 15;            // n lane
    int ty = tid >> 4;            // m lane (0..15)

    int lmA = tid >> 1;           // 0..127 (m row)
    int lkA = (tid & 1) * 4;      // k sub (0 or 4)
    int lnB = tid >> 1;
    int lkB = (tid & 1) * 4;

    const float* Xp = X + (size_t)(by * 128 + lmA) * Dd + lkA;
    const float* Wp = W + (size_t)(bx * 64 + lnB) * Dd + lkB;

    u64 acc[8][4];
#pragma unroll
    for (int i = 0; i < 8; ++i)
#pragma unroll
        for (int j = 0; j < 4; ++j) acc[i][j] = 0ull;

    for (int k0 = 0; k0 < Dd; k0 += 8) {
        float4 xa = *(const float4*)(Xp + k0);
        int kpA = lkA >> 1;
        As2[kpA][lmA]     = make_float2(xa.x, xa.y);
        As2[kpA + 1][lmA] = make_float2(xa.z, xa.w);
        if (tid < 128) {
            float4 wa = *(const float4*)(Wp + k0);
            int kpB = lkB >> 1;
            Bs2[kpB][lnB]     = make_float2(wa.x, wa.y);
            Bs2[kpB + 1][lnB] = make_float2(wa.z, wa.w);
        }
        __syncthreads();
#pragma unroll
        for (int p = 0; p < 4; ++p) {
            u64 a[8], b[4];
            ulonglong2 a0 = *(const ulonglong2*)&As2[p][ty * 8 + 0];
            ulonglong2 a1 = *(const ulonglong2*)&As2[p][ty * 8 + 2];
            ulonglong2 a2 = *(const ulonglong2*)&As2[p][ty * 8 + 4];
            ulonglong2 a3 = *(const ulonglong2*)&As2[p][ty * 8 + 6];
            a[0] = a0.x; a[1] = a0.y; a[2] = a1.x; a[3] = a1.y;
            a[4] = a2.x; a[5] = a2.y; a[6] = a3.x; a[7] = a3.y;
#pragma unroll
            for (int jj = 0; jj < 4; ++jj)
                b[jj] = *(const u64*)&Bs2[p][tx + 16 * jj];
#pragma unroll
            for (int i = 0; i < 8; ++i)
#pragma unroll
                for (int jj = 0; jj < 4; ++jj)
                    fma2(acc[i][jj], a[i], b[jj]);
        }
        __syncthreads();
    }
#pragma unroll
    for (int i = 0; i < 8; ++i) {
        size_t row = (size_t)(by * 128 + ty * 8 + i);
#pragma unroll
        for (int jj = 0; jj < 4; ++jj) {
            int col = bx * 64 + tx + 16 * jj;
            g_w[row * G2 + col] = lo_f(acc[i][jj]) + hi_f(acc[i][jj]);
        }
    }
}

// ---------------- phase 2: in-place rowwise LayerNorm over 2H ----------------
__global__ void __launch_bounds__(256) ln_rows_k(const float* __restrict__ gamma,
                                                 const float* __restrict__ beta) {
    int row = blockIdx.x;
    float* p = g_w + (size_t)row * G2;
    int tid = threadIdx.x;

    float4 v0 = *(const float4*)(p + tid * 4);
    float4 v1 = *(const float4*)(p + 1024 + tid * 4);
    float s  = v0.x + v0.y + v0.z + v0.w + v1.x + v1.y + v1.z + v1.w;
    float s2 = v0.x*v0.x + v0.y*v0.y + v0.z*v0.z + v0.w*v0.w
             + v1.x*v1.x + v1.y*v1.y + v1.z*v1.z + v1.w*v1.w;

#pragma unroll
    for (int o = 16; o > 0; o >>= 1) {
        s  += __shfl_xor_sync(0xFFFFFFFFu, s,  o);
        s2 += __shfl_xor_sync(0xFFFFFFFFu, s2, o);
    }
    __shared__ float rs[8], rs2[8];
    __shared__ float mean_s, inv_s;
    int wid = tid >> 5;
    if ((tid & 31) == 0) { rs[wid] = s; rs2[wid] = s2; }
    __syncthreads();
    if (tid == 0) {
        float S = 0.f, S2 = 0.f;
#pragma unroll
        for (int w = 0; w < 8; ++w) { S += rs[w]; S2 += rs2[w]; }
        float m  = S * (1.f / G2);
        float var = S2 * (1.f / G2) - m * m;
        mean_s = m;
        inv_s = rsqrtf(var + LN_EPS);
    }
    __syncthreads();
    float m = mean_s, inv = inv_s;

    float4 g0v = *(const float4*)(gamma + tid * 4);
    float4 b0v = *(const float4*)(beta  + tid * 4);
    float4 g1v = *(const float4*)(gamma + 1024 + tid * 4);
    float4 b1v = *(const float4*)(beta  + 1024 + tid * 4);
    float4 o0, o1;
    o0.x = (v0.x - m) * inv * g0v.x + b0v.x;
    o0.y = (v0.y - m) * inv * g0v.y + b0v.y;
    o0.z = (v0.z - m) * inv * g0v.z + b0v.z;
    o0.w = (v0.w - m) * inv * g0v.w + b0v.w;
    o1.x = (v1.x - m) * inv * g1v.x + b1v.x;
    o1.y = (v1.y - m) * inv * g1v.y + b1v.y;
    o1.z = (v1.z - m) * inv * g1v.z + b1v.z;
    o1.w = (v1.w - m) * inv * g1v.w + b1v.w;
    *(float4*)(p + tid * 4)        = o0;
    *(float4*)(p + 1024 + tid * 4) = o1;
}

// ---------------- phase 3: persistent recurrence ----------------
// 128 blocks x 512 threads. Block bid owns h cols [bid*8, bid*8+8) and the
// matching 16 U rows (8 a + 8 z), SMEM-resident.
// tid = q*16 + tb*4 + tg; q = 32-float k-slice, 4x4 reg tile of f32x2.
// SMEM columns XOR-swizzled: col(k,row) = k ^ (bit5(k)<<4) ^ (row & 12).
// Barrier: 8-way split release counters + acquire-sum poll; skipped on last
// step. Staging iteration order staggered by bid to decorrelate L2 queues.
__global__ void __launch_bounds__(512, 1) ligru_rec_k(const float* __restrict__ U,
                                                      float* __restrict__ out) {
    extern __shared__ float sm[];
    float* Us    = sm;                     // 16 * STR
    float* hs    = sm + 16 * STR;          // 16 * STR
    float* red   = hs + 16 * STR;          // 16 * RQS = 4352
    float* gates = red + 16 * RQS;         // 16 * 17

    int tid = threadIdx.x;
    int bid = blockIdx.x;
    int jbase = bid * JPB;

    // Load U slice (rows 0..7 = a-rows, 8..15 = z-rows), swizzled, once.
#pragma unroll 1
    for (int pass = 0; pass < 8; ++pass) {
        int r = pass * 2 + (tid >> 8);
        int c4 = tid & 255;
        int grow = (r < 8) ? (jbase + r) : (Hh + jbase + (r - 8));
        float4 v = *(const float4*)(U + (size_t)grow * Hh + (c4 << 2));
        int col = (c4 << 2) ^ ((c4 & 8) << 1) ^ (r & 12);
        *(float4*)(Us + r * STR + col) = v;
    }

    int q   = tid >> 4;            // 0..31 : k-slice [q*32, q*32+32)
    int tbg = tid & 15;
    int tb  = tbg >> 2;            // batches tb*4 .. tb*4+3
    int tg  = tbg & 3;             // gate rows tg*4 .. tg*4+3
    int kbase = q * 32;

    int w    = tid >> 5;           // warp id (0..15): stages k [w*64, w*64+64)
    int lane = tid & 31;

    int qx   = (q & 1) << 4;       // bit5(kbase) << 4
    int hxor = qx ^ (tb << 2);     // swizzle constant for my h rows
    int uxor = qx ^ (tg << 2);     // swizzle constant for my U rows

    const float* hpc = hs + (tb * 4) * STR + kbase;
    const float* upc = Us + (tg * 4) * STR + kbase;
    int ibase = (lane < 16) ? 0 : 2;   // rows of 4x4 tile this half-warp writes
    float* redw = red + w * RQS + tb * 68 + ibase * 16 + tg * 4;

    // gates-pass role (tid < 256)
    int wb = tid >> 4;             // batch 0..15
    int wg = tid & 15;             // gate row 0..15
    int wcol = (wg < 8) ? (jbase + wg) : (Hh + jbase + (wg - 8));
    int rbase = (wb >> 2) * 68 + (wb & 3) * 16 + (wg >> 2) * 4 + (wg & 3);

    // combine role (tid < 128): register-carried h
    int cb = tid >> 3;             // batch
    int cj = tid & 7;              // local col
    float hprev = 0.f;
    if (tid < 128) hprev = g_hbuf[0][cb * Hh + jbase + cj];

    int stag = bid & 7;            // staging stagger offset

    __syncthreads();  // Us ready

    // preload w for t=0
    float wv = 0.f;
    if (tid < 256) wv = __ldg(g_w + (size_t)(wb * Tt + 0) * G2 + wcol);

    unsigned buf = 0;
    for (int t = 0; t < Tt; ++t) {
        // Warp-local h staging: warp w loads k [w*64, w*64+64) for all 16 b,
        // iteration order rotated by bid to decorrelate the L2 read storm.
        {
            const float4* hsrc4 = (const float4*)(g_hbuf[buf]);
#pragma unroll
            for (int j0 = 0; j0 < 8; ++j0) {
                int j   = (j0 + stag) & 7;
                int idx = lane + 32 * j;      // 0..255
                int b   = idx >> 4;           // 0..15
                int f4  = idx & 15;           // 0..15
                float4 v = __ldcg(hsrc4 + b * 256 + w * 16 + f4);
                int col = (w * 64 + (f4 << 2)) ^ ((f4 & 8) << 1) ^ (b & 12);
                *(float4*)(hs + b * STR + col) = v;
            }
        }
        __syncwarp();

        // 4x4 register tile over 32 k (16 f32x2 pairs), swizzled reads
        u64 acc[4][4];
#pragma unroll
        for (int i = 0; i < 4; ++i)
#pragma unroll
            for (int j = 0; j < 4; ++j) acc[i][j] = 0ull;

#pragma unroll
        for (int kk = 0; kk < 32; kk += 4) {
            int ko_h = kk ^ hxor;
            int ko_u = kk ^ uxor;
            ulonglong2 hv[4], uv[4];
#pragma unroll
            for (int i = 0; i < 4; ++i)
                hv[i] = *(const ulonglong2*)(hpc + i * STR + ko_h);
#pragma unroll
            for (int j = 0; j < 4; ++j)
                uv[j] = *(const ulonglong2*)(upc + j * STR + ko_u);
#pragma unroll
            for (int i = 0; i < 4; ++i)
#pragma unroll
                for (int j = 0; j < 4; ++j) {
                    fma2(acc[i][j], hv[i].x, uv[j].x);
                    fma2(acc[i][j], hv[i].y, uv[j].y);
                }
        }

        // fold f32x2 halves, pre-reduce q-pair across lane^16, store 2 rows
        float c[4][4];
#pragma unroll
        for (int i = 0; i < 4; ++i)
#pragma unroll
            for (int j = 0; j < 4; ++j) {
                float v = lo_f(acc[i][j]) + hi_f(acc[i][j]);
                v += __shfl_xor_sync(0xFFFFFFFFu, v, 16);
                c[i][j] = v;
            }
#pragma unroll
        for (int ii = 0; ii < 2; ++ii) {
            int i = ibase + ii;
            *(float4*)(redw + ii * 16) = make_float4(c[i][0], c[i][1], c[i][2], c[i][3]);
        }
        __syncthreads();

        // Gates pass: sum 16 conflict-free partials + w
        if (tid < 256) {
            float s0 = 0.f, s1 = 0.f, s2 = 0.f, s3 = 0.f;
#pragma unroll
            for (int q2 = 0; q2 < 16; q2 += 4) {
                s0 += red[rbase + (q2 + 0) * RQS];
                s1 += red[rbase + (q2 + 1) * RQS];
                s2 += red[rbase + (q2 + 2) * RQS];
                s3 += red[rbase + (q2 + 3) * RQS];
            }
            gates[wg * 17 + wb] = wv + (s0 + s1) + (s2 + s3);
        }
        __syncthreads();

        // Combine: h update for my 8 columns x 16 batches (register hprev)
        float hn = 0.f;
        if (tid < 128) {
            float a  = gates[cj * 17 + cb];
            float zg = gates[(8 + cj) * 17 + cb];
            float z  = 1.f / (1.f + __expf(-zg));
            hn = z * hprev + (1.f - z) * fmaxf(a, 0.f);
            hprev = hn;
            g_hbuf[buf ^ 1u][cb * Hh + jbase + cj] = hn;
        }
        __syncthreads();   // h stores ordered before the release below

        bool last = (t + 1 == Tt);
        // Release first (split counters); overlap epilogue with the poll.
        if (!last && tid == 0) red_rel_add(&g_counts[bid & 7], 1u);
        if (tid < 128)
            out[(size_t)cb * (Tt * Hh) + (size_t)t * Hh + jbase + cj] = hn;
        float wv_n = 0.f;
        if (!last && tid < 256)
            wv_n = __ldg(g_w + (size_t)(wb * Tt + (t + 1)) * G2 + wcol);
        if (!last && tid == 0) {
            unsigned target = (unsigned)(t + 1) * NB;
            for (;;) {
                unsigned s = 0;
#pragma unroll
                for (int i = 0; i < 8; ++i) s += ld_acq(&g_counts[i]);
                if (s >= target) break;
            }
        }
        __syncthreads();

        wv = wv_n;
        buf ^= 1u;
    }
}

// ---------------- launch ----------------
extern "C" void kernel_launch(void* const* d_in, const int* in_sizes, int n_in,
                              void* d_out, int out_size) {
    const float* x     = (const float*)d_in[0];   // [16,512,512]
    const float* W_w   = (const float*)d_in[1];   // [2048,512]
    const float* U_w   = (const float*)d_in[2];   // [2048,1024]
    const float* gamma = (const float*)d_in[3];   // [2048]
    const float* beta  = (const float*)d_in[4];   // [2048]
    const float* h0    = (const float*)d_in[5];   // [1,1024]
    float* out = (float*)d_out;                   // [16,512,1024]

    const int smem_rec = (2 * 16 * STR + 16 * RQS + 16 * 17 + 16) * (int)sizeof(float);
    cudaFuncSetAttribute(ligru_rec_k, cudaFuncAttributeMaxDynamicSharedMemorySize,
                         smem_rec);

    init_state_k<<<64, 256>>>(h0);

    dim3 gg(G2 / 64, (Bb * Tt) / 128);
    gemm_xw_k<<<gg, 256>>>(x, W_w);

    ln_rows_k<<<Bb * Tt, 256>>>(gamma, beta);

    ligru_rec_k<<<NB, 512, smem_rec>>>(U_w, out);
}

// round 10
// speedup vs baseline: 1.2906x; 1.2906x over previous
#include <cuda_runtime.h>
#include <cstdint>
#include <cstddef>

// Problem shapes (fixed)
#define Tt   512
#define Bb   16
#define Dd   512
#define Hh   1024
#define G2   2048            // 2*H
#define NB   128             // persistent worker blocks
#define JPB  8               // h columns per block (Hh / NB)
#define STR  1028            // smem row stride in floats (padded)
#define RQS  272             // red per-q2 stride (floats)
#define LN_EPS 1e-5f

typedef unsigned long long u64;

__device__ __forceinline__ void fma2(u64& d, u64 a, u64 b) {
    asm("fma.rn.f32x2 %0, %1, %2, %0;" : "+l"(d) : "l"(a), "l"(b));
}
__device__ __forceinline__ void red_rel_add(unsigned* p, unsigned v) {
    asm volatile("red.release.gpu.global.add.u32 [%0], %1;" :: "l"(p), "r"(v) : "memory");
}
__device__ __forceinline__ unsigned ld_acq(unsigned* p) {
    unsigned v;
    asm volatile("ld.acquire.gpu.global.u32 %0, [%1];" : "=r"(v) : "l"(p) : "memory");
    return v;
}
__device__ __forceinline__ float lo_f(u64 v) { return __uint_as_float((unsigned)v); }
__device__ __forceinline__ float hi_f(u64 v) { return __uint_as_float((unsigned)(v >> 32)); }

// ---------------- device scratch (allocation-free) ----------------
__device__ float    g_w[(size_t)Bb * Tt * G2];   // 64 MB: LN'd projection
__device__ float    g_hbuf[2][Bb * Hh];          // double-buffered hidden state
__device__ unsigned g_count;                     // barrier counter (monotonic)

// ---------------- init: reset barrier state + h0 ----------------
__global__ void init_state_k(const float* __restrict__ h0) {
    int i = blockIdx.x * blockDim.x + threadIdx.x;
    if (i < Bb * Hh) g_hbuf[0][i] = h0[i & (Hh - 1)];   // broadcast h0 over batch
    if (i == 0)      g_count = 0u;
}

// ---------------- phase 1: g_w = x @ W^T  (f32x2 tiled GEMM) ----------------
__global__ void __launch_bounds__(256) gemm_xw_k(const float* __restrict__ X,
                                                 const float* __restrict__ W) {
    __shared__ float2 As2[4][128];
    __shared__ float2 Bs2[4][66];

    int tid = threadIdx.x;
    int bx = blockIdx.x;          // n tile (32)
    int by = blockIdx.y;          // m tile (64)
    int tx = tid & 15;            // n lane
    int ty = tid >> 4;            // m lane (0..15)

    int lmA = tid >> 1;           // 0..127 (m row)
    int lkA = (tid & 1) * 4;      // k sub (0 or 4)
    int lnB = tid >> 1;
    int lkB = (tid & 1) * 4;

    const float* Xp = X + (size_t)(by * 128 + lmA) * Dd + lkA;
    const float* Wp = W + (size_t)(bx * 64 + lnB) * Dd + lkB;

    u64 acc[8][4];
#pragma unroll
    for (int i = 0; i < 8; ++i)
#pragma unroll
        for (int j = 0; j < 4; ++j) acc[i][j] = 0ull;

    for (int k0 = 0; k0 < Dd; k0 += 8) {
        float4 xa = *(const float4*)(Xp + k0);
        int kpA = lkA >> 1;
        As2[kpA][lmA]     = make_float2(xa.x, xa.y);
        As2[kpA + 1][lmA] = make_float2(xa.z, xa.w);
        if (tid < 128) {
            float4 wa = *(const float4*)(Wp + k0);
            int kpB = lkB >> 1;
            Bs2[kpB][lnB]     = make_float2(wa.x, wa.y);
            Bs2[kpB + 1][lnB] = make_float2(wa.z, wa.w);
        }
        __syncthreads();
#pragma unroll
        for (int p = 0; p < 4; ++p) {
            u64 a[8], b[4];
            ulonglong2 a0 = *(const ulonglong2*)&As2[p][ty * 8 + 0];
            ulonglong2 a1 = *(const ulonglong2*)&As2[p][ty * 8 + 2];
            ulonglong2 a2 = *(const ulonglong2*)&As2[p][ty * 8 + 4];
            ulonglong2 a3 = *(const ulonglong2*)&As2[p][ty * 8 + 6];
            a[0] = a0.x; a[1] = a0.y; a[2] = a1.x; a[3] = a1.y;
            a[4] = a2.x; a[5] = a2.y; a[6] = a3.x; a[7] = a3.y;
#pragma unroll
            for (int jj = 0; jj < 4; ++jj)
                b[jj] = *(const u64*)&Bs2[p][tx + 16 * jj];
#pragma unroll
            for (int i = 0; i < 8; ++i)
#pragma unroll
                for (int jj = 0; jj < 4; ++jj)
                    fma2(acc[i][jj], a[i], b[jj]);
        }
        __syncthreads();
    }
#pragma unroll
    for (int i = 0; i < 8; ++i) {
        size_t row = (size_t)(by * 128 + ty * 8 + i);
#pragma unroll
        for (int jj = 0; jj < 4; ++jj) {
            int col = bx * 64 + tx + 16 * jj;
            g_w[row * G2 + col] = lo_f(acc[i][jj]) + hi_f(acc[i][jj]);
        }
    }
}

// ---------------- phase 2: in-place rowwise LayerNorm over 2H ----------------
__global__ void __launch_bounds__(256) ln_rows_k(const float* __restrict__ gamma,
                                                 const float* __restrict__ beta) {
    int row = blockIdx.x;
    float* p = g_w + (size_t)row * G2;
    int tid = threadIdx.x;

    float4 v0 = *(const float4*)(p + tid * 4);
    float4 v1 = *(const float4*)(p + 1024 + tid * 4);
    float s  = v0.x + v0.y + v0.z + v0.w + v1.x + v1.y + v1.z + v1.w;
    float s2 = v0.x*v0.x + v0.y*v0.y + v0.z*v0.z + v0.w*v0.w
             + v1.x*v1.x + v1.y*v1.y + v1.z*v1.z + v1.w*v1.w;

#pragma unroll
    for (int o = 16; o > 0; o >>= 1) {
        s  += __shfl_xor_sync(0xFFFFFFFFu, s,  o);
        s2 += __shfl_xor_sync(0xFFFFFFFFu, s2, o);
    }
    __shared__ float rs[8], rs2[8];
    __shared__ float mean_s, inv_s;
    int wid = tid >> 5;
    if ((tid & 31) == 0) { rs[wid] = s; rs2[wid] = s2; }
    __syncthreads();
    if (tid == 0) {
        float S = 0.f, S2 = 0.f;
#pragma unroll
        for (int w = 0; w < 8; ++w) { S += rs[w]; S2 += rs2[w]; }
        float m  = S * (1.f / G2);
        float var = S2 * (1.f / G2) - m * m;
        mean_s = m;
        inv_s = rsqrtf(var + LN_EPS);
    }
    __syncthreads();
    float m = mean_s, inv = inv_s;

    float4 g0v = *(const float4*)(gamma + tid * 4);
    float4 b0v = *(const float4*)(beta  + tid * 4);
    float4 g1v = *(const float4*)(gamma + 1024 + tid * 4);
    float4 b1v = *(const float4*)(beta  + 1024 + tid * 4);
    float4 o0, o1;
    o0.x = (v0.x - m) * inv * g0v.x + b0v.x;
    o0.y = (v0.y - m) * inv * g0v.y + b0v.y;
    o0.z = (v0.z - m) * inv * g0v.z + b0v.z;
    o0.w = (v0.w - m) * inv * g0v.w + b0v.w;
    o1.x = (v1.x - m) * inv * g1v.x + b1v.x;
    o1.y = (v1.y - m) * inv * g1v.y + b1v.y;
    o1.z = (v1.z - m) * inv * g1v.z + b1v.z;
    o1.w = (v1.w - m) * inv * g1v.w + b1v.w;
    *(float4*)(p + tid * 4)        = o0;
    *(float4*)(p + 1024 + tid * 4) = o1;
}

// ---------------- phase 3: persistent recurrence ----------------
// 128 blocks x 512 threads. Block bid owns h cols [bid*8, bid*8+8) and the
// matching 16 U rows (8 a + 8 z), SMEM-resident.
// tid = q*16 + tb*4 + tg; q = 32-float k-slice, 4x4 reg tile of f32x2.
// SMEM columns XOR-swizzled: col(k,row) = k ^ (bit5(k)<<4) ^ (row & 12).
// Epilogue merged: 128 threads reduce their a- AND z-gate rows from red and
// combine in one phase (no gates array, one fewer syncthreads).
// Barrier: single-counter REDG release + single ld.acquire poll (R7 style).
__global__ void __launch_bounds__(512, 1) ligru_rec_k(const float* __restrict__ U,
                                                      float* __restrict__ out) {
    extern __shared__ float sm[];
    float* Us    = sm;                     // 16 * STR
    float* hs    = sm + 16 * STR;          // 16 * STR
    float* red   = hs + 16 * STR;          // 16 * RQS = 4352

    int tid = threadIdx.x;
    int bid = blockIdx.x;
    int jbase = bid * JPB;

    // Load U slice (rows 0..7 = a-rows, 8..15 = z-rows), swizzled, once.
#pragma unroll 1
    for (int pass = 0; pass < 8; ++pass) {
        int r = pass * 2 + (tid >> 8);
        int c4 = tid & 255;
        int grow = (r < 8) ? (jbase + r) : (Hh + jbase + (r - 8));
        float4 v = *(const float4*)(U + (size_t)grow * Hh + (c4 << 2));
        int col = (c4 << 2) ^ ((c4 & 8) << 1) ^ (r & 12);
        *(float4*)(Us + r * STR + col) = v;
    }

    int q   = tid >> 4;            // 0..31 : k-slice [q*32, q*32+32)
    int tbg = tid & 15;
    int tb  = tbg >> 2;            // batches tb*4 .. tb*4+3
    int tg  = tbg & 3;             // gate rows tg*4 .. tg*4+3
    int kbase = q * 32;

    int w    = tid >> 5;           // warp id (0..15): stages k [w*64, w*64+64)
    int lane = tid & 31;

    int qx   = (q & 1) << 4;       // bit5(kbase) << 4
    int hxor = qx ^ (tb << 2);     // swizzle constant for my h rows
    int uxor = qx ^ (tg << 2);     // swizzle constant for my U rows

    const float* hpc = hs + (tb * 4) * STR + kbase;
    const float* upc = Us + (tg * 4) * STR + kbase;
    int ibase = (lane < 16) ? 0 : 2;   // rows of 4x4 tile this half-warp writes
    float* redw = red + w * RQS + tb * 68 + ibase * 16 + tg * 4;

    // merged epilogue role (tid < 128): batch cb, local col cj
    int cb = tid >> 3;             // batch 0..15
    int cj = tid & 7;              // local col 0..7
    // red index for (batch cb, gate row r): (cb>>2)*68 + (cb&3)*16 + (r>>2)*4 + (r&3)
    int rb_a = (cb >> 2) * 68 + (cb & 3) * 16 + (cj >> 2) * 4 + (cj & 3);  // row cj
    // z row = 8 + cj -> adds exactly +8 to the row term
    size_t wrow = (size_t)cb * Tt * G2;
    int wcol_a = jbase + cj;
    int wcol_z = Hh + jbase + cj;
    float hprev = 0.f;
    if (tid < 128) hprev = g_hbuf[0][cb * Hh + jbase + cj];

    __syncthreads();  // Us ready

    // preload w for t=0
    float wv_a = 0.f, wv_z = 0.f;
    if (tid < 128) {
        wv_a = __ldg(g_w + wrow + wcol_a);
        wv_z = __ldg(g_w + wrow + wcol_z);
    }

    unsigned buf = 0;
    for (int t = 0; t < Tt; ++t) {
        // Warp-local h staging: warp w loads k [w*64, w*64+64) for all 16 b,
        // storing at swizzled columns.
        {
            const float4* hsrc4 = (const float4*)(g_hbuf[buf]);
#pragma unroll
            for (int j = 0; j < 8; ++j) {
                int idx = lane + 32 * j;      // 0..255
                int b   = idx >> 4;           // 0..15
                int f4  = idx & 15;           // 0..15
                float4 v = __ldcg(hsrc4 + b * 256 + w * 16 + f4);
                int col = (w * 64 + (f4 << 2)) ^ ((f4 & 8) << 1) ^ (b & 12);
                *(float4*)(hs + b * STR + col) = v;
            }
        }
        __syncwarp();

        // 4x4 register tile over 32 k (16 f32x2 pairs), swizzled reads
        u64 acc[4][4];
#pragma unroll
        for (int i = 0; i < 4; ++i)
#pragma unroll
            for (int j = 0; j < 4; ++j) acc[i][j] = 0ull;

#pragma unroll
        for (int kk = 0; kk < 32; kk += 4) {
            int ko_h = kk ^ hxor;
            int ko_u = kk ^ uxor;
            ulonglong2 hv[4], uv[4];
#pragma unroll
            for (int i = 0; i < 4; ++i)
                hv[i] = *(const ulonglong2*)(hpc + i * STR + ko_h);
#pragma unroll
            for (int j = 0; j < 4; ++j)
                uv[j] = *(const ulonglong2*)(upc + j * STR + ko_u);
#pragma unroll
            for (int i = 0; i < 4; ++i)
#pragma unroll
                for (int j = 0; j < 4; ++j) {
                    fma2(acc[i][j], hv[i].x, uv[j].x);
                    fma2(acc[i][j], hv[i].y, uv[j].y);
                }
        }

        // fold f32x2 halves, pre-reduce q-pair across lane^16, store 2 rows
        float c[4][4];
#pragma unroll
        for (int i = 0; i < 4; ++i)
#pragma unroll
            for (int j = 0; j < 4; ++j) {
                float v = lo_f(acc[i][j]) + hi_f(acc[i][j]);
                v += __shfl_xor_sync(0xFFFFFFFFu, v, 16);
                c[i][j] = v;
            }
#pragma unroll
        for (int ii = 0; ii < 2; ++ii) {
            int i = ibase + ii;
            *(float4*)(redw + ii * 16) = make_float4(c[i][0], c[i][1], c[i][2], c[i][3]);
        }
        __syncthreads();   // red ready

        // Merged gates+combine (tid < 128): reduce a & z rows, update h.
        float hn = 0.f;
        if (tid < 128) {
            float a0 = 0.f, a1 = 0.f, z0 = 0.f, z1 = 0.f;
#pragma unroll
            for (int q2 = 0; q2 < 16; q2 += 2) {
                a0 += red[rb_a     + (q2 + 0) * RQS];
                a1 += red[rb_a     + (q2 + 1) * RQS];
                z0 += red[rb_a + 8 + (q2 + 0) * RQS];
                z1 += red[rb_a + 8 + (q2 + 1) * RQS];
            }
            float a  = wv_a + a0 + a1;
            float zg = wv_z + z0 + z1;
            float z  = 1.f / (1.f + __expf(-zg));
            hn = z * hprev + (1.f - z) * fmaxf(a, 0.f);
            hprev = hn;
            g_hbuf[buf ^ 1u][cb * Hh + jbase + cj] = hn;
        }
        __syncthreads();   // h stores ordered before the release below

        bool last = (t + 1 == Tt);
        // Release first; overlap out-store + next-w prefetch with the poll.
        if (!last && tid == 0) red_rel_add(&g_count, 1u);
        if (tid < 128) {
            out[(size_t)cb * (Tt * Hh) + (size_t)t * Hh + jbase + cj] = hn;
            if (!last) {
                wv_a = __ldg(g_w + wrow + (size_t)(t + 1) * G2 + wcol_a);
                wv_z = __ldg(g_w + wrow + (size_t)(t + 1) * G2 + wcol_z);
            }
        }
        if (!last && tid == 0) {
            unsigned target = (unsigned)(t + 1) * NB;
            while (ld_acq(&g_count) < target) { }
        }
        __syncthreads();

        buf ^= 1u;
    }
}

// ---------------- launch ----------------
extern "C" void kernel_launch(void* const* d_in, const int* in_sizes, int n_in,
                              void* d_out, int out_size) {
    const float* x     = (const float*)d_in[0];   // [16,512,512]
    const float* W_w   = (const float*)d_in[1];   // [2048,512]
    const float* U_w   = (const float*)d_in[2];   // [2048,1024]
    const float* gamma = (const float*)d_in[3];   // [2048]
    const float* beta  = (const float*)d_in[4];   // [2048]
    const float* h0    = (const float*)d_in[5];   // [1,1024]
    float* out = (float*)d_out;                   // [16,512,1024]

    const int smem_rec = (2 * 16 * STR + 16 * RQS + 16) * (int)sizeof(float);
    cudaFuncSetAttribute(ligru_rec_k, cudaFuncAttributeMaxDynamicSharedMemorySize,
                         smem_rec);

    init_state_k<<<64, 256>>>(h0);

    dim3 gg(G2 / 64, (Bb * Tt) / 128);
    gemm_xw_k<<<gg, 256>>>(x, W_w);

    ln_rows_k<<<Bb * Tt, 256>>>(gamma, beta);

    ligru_rec_k<<<NB, 512, smem_rec>>>(U_w, out);
}

// round 11
// speedup vs baseline: 1.3314x; 1.0316x over previous
#include <cuda_runtime.h>
#include <cstdint>
#include <cstddef>

// Problem shapes (fixed)
#define Tt   512
#define Bb   16
#define Dd   512
#define Hh   1024
#define G2   2048            // 2*H
#define NB   128             // persistent worker blocks
#define JPB  8               // h columns per block (Hh / NB)
#define STR  1028            // smem row stride in floats (padded)
#define RQS  272             // red per-q2 stride (floats)
#define LN_EPS 1e-5f

typedef unsigned long long u64;

__device__ __forceinline__ void fma2(u64& d, u64 a, u64 b) {
    asm("fma.rn.f32x2 %0, %1, %2, %0;" : "+l"(d) : "l"(a), "l"(b));
}
__device__ __forceinline__ void red_rel_add(unsigned* p, unsigned v) {
    asm volatile("red.release.gpu.global.add.u32 [%0], %1;" :: "l"(p), "r"(v) : "memory");
}
__device__ __forceinline__ unsigned ld_acq(unsigned* p) {
    unsigned v;
    asm volatile("ld.acquire.gpu.global.u32 %0, [%1];" : "=r"(v) : "l"(p) : "memory");
    return v;
}
__device__ __forceinline__ float lo_f(u64 v) { return __uint_as_float((unsigned)v); }
__device__ __forceinline__ float hi_f(u64 v) { return __uint_as_float((unsigned)(v >> 32)); }

// ---------------- device scratch (allocation-free) ----------------
__device__ float    g_w[(size_t)Bb * Tt * G2];   // 64 MB: LN'd projection
__device__ float    g_hbuf[2][Bb * Hh];          // double-buffered hidden state
__device__ unsigned g_count;                     // barrier counter (monotonic)

// ---------------- init: reset barrier state + h0 ----------------
__global__ void init_state_k(const float* __restrict__ h0) {
    int i = blockIdx.x * blockDim.x + threadIdx.x;
    if (i < Bb * Hh) g_hbuf[0][i] = h0[i & (Hh - 1)];   // broadcast h0 over batch
    if (i == 0)      g_count = 0u;
}

// ---------------- phase 1: g_w = x @ W^T  (f32x2 tiled GEMM) ----------------
// Register double-buffered: next k-tile's LDGs issue right after the
// post-store barrier and overlap the 4x(32 FFMA2) compute phase.
__global__ void __launch_bounds__(256) gemm_xw_k(const float* __restrict__ X,
                                                 const float* __restrict__ W) {
    __shared__ float2 As2[4][128];
    __shared__ float2 Bs2[4][66];

    int tid = threadIdx.x;
    int bx = blockIdx.x;          // n tile (32)
    int by = blockIdx.y;          // m tile (64)
    int tx = tid & 15;            // n lane
    int ty = tid >> 4;            // m lane (0..15)

    int lmA = tid >> 1;           // 0..127 (m row)
    int lkA = (tid & 1) * 4;      // k sub (0 or 4)
    int lnB = tid >> 1;
    int lkB = (tid & 1) * 4;

    const float* Xp = X + (size_t)(by * 128 + lmA) * Dd + lkA;
    const float* Wp = W + (size_t)(bx * 64 + lnB) * Dd + lkB;

    u64 acc[8][4];
#pragma unroll
    for (int i = 0; i < 8; ++i)
#pragma unroll
        for (int j = 0; j < 4; ++j) acc[i][j] = 0ull;

    int kpA = lkA >> 1;
    int kpB = lkB >> 1;

    // preload k-tile 0
    float4 xa = *(const float4*)(Xp);
    float4 wa = make_float4(0.f, 0.f, 0.f, 0.f);
    if (tid < 128) wa = *(const float4*)(Wp);

    for (int k0 = 0; k0 < Dd; k0 += 8) {
        // store current tile
        As2[kpA][lmA]     = make_float2(xa.x, xa.y);
        As2[kpA + 1][lmA] = make_float2(xa.z, xa.w);
        if (tid < 128) {
            Bs2[kpB][lnB]     = make_float2(wa.x, wa.y);
            Bs2[kpB + 1][lnB] = make_float2(wa.z, wa.w);
        }
        __syncthreads();

        // prefetch next tile (overlaps the compute below)
        if (k0 + 8 < Dd) {
            xa = *(const float4*)(Xp + k0 + 8);
            if (tid < 128) wa = *(const float4*)(Wp + k0 + 8);
        }

#pragma unroll
        for (int p = 0; p < 4; ++p) {
            u64 a[8], b[4];
            ulonglong2 a0 = *(const ulonglong2*)&As2[p][ty * 8 + 0];
            ulonglong2 a1 = *(const ulonglong2*)&As2[p][ty * 8 + 2];
            ulonglong2 a2 = *(const ulonglong2*)&As2[p][ty * 8 + 4];
            ulonglong2 a3 = *(const ulonglong2*)&As2[p][ty * 8 + 6];
            a[0] = a0.x; a[1] = a0.y; a[2] = a1.x; a[3] = a1.y;
            a[4] = a2.x; a[5] = a2.y; a[6] = a3.x; a[7] = a3.y;
#pragma unroll
            for (int jj = 0; jj < 4; ++jj)
                b[jj] = *(const u64*)&Bs2[p][tx + 16 * jj];
#pragma unroll
            for (int i = 0; i < 8; ++i)
#pragma unroll
                for (int jj = 0; jj < 4; ++jj)
                    fma2(acc[i][jj], a[i], b[jj]);
        }
        __syncthreads();
    }
#pragma unroll
    for (int i = 0; i < 8; ++i) {
        size_t row = (size_t)(by * 128 + ty * 8 + i);
#pragma unroll
        for (int jj = 0; jj < 4; ++jj) {
            int col = bx * 64 + tx + 16 * jj;
            g_w[row * G2 + col] = lo_f(acc[i][jj]) + hi_f(acc[i][jj]);
        }
    }
}

// ---------------- phase 2: in-place rowwise LayerNorm over 2H ----------------
__global__ void __launch_bounds__(256) ln_rows_k(const float* __restrict__ gamma,
                                                 const float* __restrict__ beta) {
    int row = blockIdx.x;
    float* p = g_w + (size_t)row * G2;
    int tid = threadIdx.x;

    float4 v0 = *(const float4*)(p + tid * 4);
    float4 v1 = *(const float4*)(p + 1024 + tid * 4);
    float s  = v0.x + v0.y + v0.z + v0.w + v1.x + v1.y + v1.z + v1.w;
    float s2 = v0.x*v0.x + v0.y*v0.y + v0.z*v0.z + v0.w*v0.w
             + v1.x*v1.x + v1.y*v1.y + v1.z*v1.z + v1.w*v1.w;

#pragma unroll
    for (int o = 16; o > 0; o >>= 1) {
        s  += __shfl_xor_sync(0xFFFFFFFFu, s,  o);
        s2 += __shfl_xor_sync(0xFFFFFFFFu, s2, o);
    }
    __shared__ float rs[8], rs2[8];
    __shared__ float mean_s, inv_s;
    int wid = tid >> 5;
    if ((tid & 31) == 0) { rs[wid] = s; rs2[wid] = s2; }
    __syncthreads();
    if (tid == 0) {
        float S = 0.f, S2 = 0.f;
#pragma unroll
        for (int w = 0; w < 8; ++w) { S += rs[w]; S2 += rs2[w]; }
        float m  = S * (1.f / G2);
        float var = S2 * (1.f / G2) - m * m;
        mean_s = m;
        inv_s = rsqrtf(var + LN_EPS);
    }
    __syncthreads();
    float m = mean_s, inv = inv_s;

    float4 g0v = *(const float4*)(gamma + tid * 4);
    float4 b0v = *(const float4*)(beta  + tid * 4);
    float4 g1v = *(const float4*)(gamma + 1024 + tid * 4);
    float4 b1v = *(const float4*)(beta  + 1024 + tid * 4);
    float4 o0, o1;
    o0.x = (v0.x - m) * inv * g0v.x + b0v.x;
    o0.y = (v0.y - m) * inv * g0v.y + b0v.y;
    o0.z = (v0.z - m) * inv * g0v.z + b0v.z;
    o0.w = (v0.w - m) * inv * g0v.w + b0v.w;
    o1.x = (v1.x - m) * inv * g1v.x + b1v.x;
    o1.y = (v1.y - m) * inv * g1v.y + b1v.y;
    o1.z = (v1.z - m) * inv * g1v.z + b1v.z;
    o1.w = (v1.w - m) * inv * g1v.w + b1v.w;
    *(float4*)(p + tid * 4)        = o0;
    *(float4*)(p + 1024 + tid * 4) = o1;
}

// ---------------- phase 3: persistent recurrence (R7, proven) ----------------
// 128 blocks x 512 threads. Block bid owns h cols [bid*8, bid*8+8) and the
// matching 16 U rows (8 a + 8 z), SMEM-resident.
// tid = q*16 + tb*4 + tg; q = 32-float k-slice, 4x4 reg tile of f32x2.
// SMEM columns XOR-swizzled: col(k,row) = k ^ (bit5(k)<<4) ^ (row & 12).
// Barrier: single-counter REDG release + single ld.acquire poll; skipped on
// the final step.
__global__ void __launch_bounds__(512, 1) ligru_rec_k(const float* __restrict__ U,
                                                      float* __restrict__ out) {
    extern __shared__ float sm[];
    float* Us    = sm;                     // 16 * STR
    float* hs    = sm + 16 * STR;          // 16 * STR
    float* red   = hs + 16 * STR;          // 16 * RQS = 4352
    float* gates = red + 16 * RQS;         // 16 * 17

    int tid = threadIdx.x;
    int bid = blockIdx.x;
    int jbase = bid * JPB;

    // Load U slice (rows 0..7 = a-rows, 8..15 = z-rows), swizzled, once.
#pragma unroll 1
    for (int pass = 0; pass < 8; ++pass) {
        int r = pass * 2 + (tid >> 8);
        int c4 = tid & 255;
        int grow = (r < 8) ? (jbase + r) : (Hh + jbase + (r - 8));
        float4 v = *(const float4*)(U + (size_t)grow * Hh + (c4 << 2));
        int col = (c4 << 2) ^ ((c4 & 8) << 1) ^ (r & 12);
        *(float4*)(Us + r * STR + col) = v;
    }

    int q   = tid >> 4;            // 0..31 : k-slice [q*32, q*32+32)
    int tbg = tid & 15;
    int tb  = tbg >> 2;            // batches tb*4 .. tb*4+3
    int tg  = tbg & 3;             // gate rows tg*4 .. tg*4+3
    int kbase = q * 32;

    int w    = tid >> 5;           // warp id (0..15): stages k [w*64, w*64+64)
    int lane = tid & 31;

    int qx   = (q & 1) << 4;       // bit5(kbase) << 4
    int hxor = qx ^ (tb << 2);     // swizzle constant for my h rows
    int uxor = qx ^ (tg << 2);     // swizzle constant for my U rows

    const float* hpc = hs + (tb * 4) * STR + kbase;
    const float* upc = Us + (tg * 4) * STR + kbase;
    int ibase = (lane < 16) ? 0 : 2;   // rows of 4x4 tile this half-warp writes
    float* redw = red + w * RQS + tb * 68 + ibase * 16 + tg * 4;

    // gates-pass role (tid < 256)
    int wb = tid >> 4;             // batch 0..15
    int wg = tid & 15;             // gate row 0..15
    int wcol = (wg < 8) ? (jbase + wg) : (Hh + jbase + (wg - 8));
    int rbase = (wb >> 2) * 68 + (wb & 3) * 16 + (wg >> 2) * 4 + (wg & 3);

    // combine role (tid < 128): register-carried h
    int cb = tid >> 3;             // batch
    int cj = tid & 7;              // local col
    float hprev = 0.f;
    if (tid < 128) hprev = g_hbuf[0][cb * Hh + jbase + cj];

    __syncthreads();  // Us ready

    // preload w for t=0
    float wv = 0.f;
    if (tid < 256) wv = __ldg(g_w + (size_t)(wb * Tt + 0) * G2 + wcol);

    unsigned buf = 0;
    for (int t = 0; t < Tt; ++t) {
        // Warp-local h staging: warp w loads k [w*64, w*64+64) for all 16 b,
        // storing at swizzled columns.
        {
            const float4* hsrc4 = (const float4*)(g_hbuf[buf]);
#pragma unroll
            for (int j = 0; j < 8; ++j) {
                int idx = lane + 32 * j;      // 0..255
                int b   = idx >> 4;           // 0..15
                int f4  = idx & 15;           // 0..15
                float4 v = __ldcg(hsrc4 + b * 256 + w * 16 + f4);
                int col = (w * 64 + (f4 << 2)) ^ ((f4 & 8) << 1) ^ (b & 12);
                *(float4*)(hs + b * STR + col) = v;
            }
        }
        __syncwarp();

        // 4x4 register tile over 32 k (16 f32x2 pairs), swizzled reads
        u64 acc[4][4];
#pragma unroll
        for (int i = 0; i < 4; ++i)
#pragma unroll
            for (int j = 0; j < 4; ++j) acc[i][j] = 0ull;

#pragma unroll
        for (int kk = 0; kk < 32; kk += 4) {
            int ko_h = kk ^ hxor;
            int ko_u = kk ^ uxor;
            ulonglong2 hv[4], uv[4];
#pragma unroll
            for (int i = 0; i < 4; ++i)
                hv[i] = *(const ulonglong2*)(hpc + i * STR + ko_h);
#pragma unroll
            for (int j = 0; j < 4; ++j)
                uv[j] = *(const ulonglong2*)(upc + j * STR + ko_u);
#pragma unroll
            for (int i = 0; i < 4; ++i)
#pragma unroll
                for (int j = 0; j < 4; ++j) {
                    fma2(acc[i][j], hv[i].x, uv[j].x);
                    fma2(acc[i][j], hv[i].y, uv[j].y);
                }
        }

        // fold f32x2 halves, pre-reduce q-pair across lane^16, store 2 rows
        float c[4][4];
#pragma unroll
        for (int i = 0; i < 4; ++i)
#pragma unroll
            for (int j = 0; j < 4; ++j) {
                float v = lo_f(acc[i][j]) + hi_f(acc[i][j]);
                v += __shfl_xor_sync(0xFFFFFFFFu, v, 16);
                c[i][j] = v;
            }
#pragma unroll
        for (int ii = 0; ii < 2; ++ii) {
            int i = ibase + ii;
            *(float4*)(redw + ii * 16) = make_float4(c[i][0], c[i][1], c[i][2], c[i][3]);
        }
        __syncthreads();

        // Gates pass: sum 16 conflict-free partials + w
        if (tid < 256) {
            float s0 = 0.f, s1 = 0.f, s2 = 0.f, s3 = 0.f;
#pragma unroll
            for (int q2 = 0; q2 < 16; q2 += 4) {
                s0 += red[rbase + (q2 + 0) * RQS];
                s1 += red[rbase + (q2 + 1) * RQS];
                s2 += red[rbase + (q2 + 2) * RQS];
                s3 += red[rbase + (q2 + 3) * RQS];
            }
            gates[wg * 17 + wb] = wv + (s0 + s1) + (s2 + s3);
        }
        __syncthreads();

        // Combine: h update for my 8 columns x 16 batches (register hprev)
        float hn = 0.f;
        if (tid < 128) {
            float a  = gates[cj * 17 + cb];
            float zg = gates[(8 + cj) * 17 + cb];
            float z  = 1.f / (1.f + __expf(-zg));
            hn = z * hprev + (1.f - z) * fmaxf(a, 0.f);
            hprev = hn;
            g_hbuf[buf ^ 1u][cb * Hh + jbase + cj] = hn;
        }
        __syncthreads();   // h stores ordered before the release below

        bool last = (t + 1 == Tt);
        // Release first; overlap out-store + next-w prefetch with the poll.
        if (!last && tid == 0) red_rel_add(&g_count, 1u);
        if (tid < 128)
            out[(size_t)cb * (Tt * Hh) + (size_t)t * Hh + jbase + cj] = hn;
        float wv_n = 0.f;
        if (!last && tid < 256)
            wv_n = __ldg(g_w + (size_t)(wb * Tt + (t + 1)) * G2 + wcol);
        if (!last && tid == 0) {
            unsigned target = (unsigned)(t + 1) * NB;
            while (ld_acq(&g_count) < target) { }
        }
        __syncthreads();

        wv = wv_n;
        buf ^= 1u;
    }
}

// ---------------- launch ----------------
extern "C" void kernel_launch(void* const* d_in, const int* in_sizes, int n_in,
                              void* d_out, int out_size) {
    const float* x     = (const float*)d_in[0];   // [16,512,512]
    const float* W_w   = (const float*)d_in[1];   // [2048,512]
    const float* U_w   = (const float*)d_in[2];   // [2048,1024]
    const float* gamma = (const float*)d_in[3];   // [2048]
    const float* beta  = (const float*)d_in[4];   // [2048]
    const float* h0    = (const float*)d_in[5];   // [1,1024]
    float* out = (float*)d_out;                   // [16,512,1024]

    const int smem_rec = (2 * 16 * STR + 16 * RQS + 16 * 17 + 16) * (int)sizeof(float);
    cudaFuncSetAttribute(ligru_rec_k, cudaFuncAttributeMaxDynamicSharedMemorySize,
                         smem_rec);

    init_state_k<<<64, 256>>>(h0);

    dim3 gg(G2 / 64, (Bb * Tt) / 128);
    gemm_xw_k<<<gg, 256>>>(x, W_w);

    ln_rows_k<<<Bb * Tt, 256>>>(gamma, beta);

    ligru_rec_k<<<NB, 512, smem_rec>>>(U_w, out);
}

// round 14
// speedup vs baseline: 1.3900x; 1.0440x over previous
#include <cuda_runtime.h>
#include <cstdint>
#include <cstddef>

// Problem shapes (fixed)
#define Tt   512
#define Bb   16
#define Dd   512
#define Hh   1024
#define G2   2048            // 2*H
#define NB   128             // persistent worker blocks
#define JPB  8               // h columns per block (Hh / NB)
#define STR  1028            // smem row stride in floats (padded)
#define RQS  272             // red per-q2 stride (floats)
#define LN_EPS 1e-5f

typedef unsigned long long u64;

__device__ __forceinline__ void fma2(u64& d, u64 a, u64 b) {
    asm("fma.rn.f32x2 %0, %1, %2, %0;" : "+l"(d) : "l"(a), "l"(b));
}
__device__ __forceinline__ void red_rel_add(unsigned* p, unsigned v) {
    asm volatile("red.release.gpu.global.add.u32 [%0], %1;" :: "l"(p), "r"(v) : "memory");
}
__device__ __forceinline__ unsigned ld_acq(unsigned* p) {
    unsigned v;
    asm volatile("ld.acquire.gpu.global.u32 %0, [%1];" : "=r"(v) : "l"(p) : "memory");
    return v;
}
__device__ __forceinline__ float lo_f(u64 v) { return __uint_as_float((unsigned)v); }
__device__ __forceinline__ float hi_f(u64 v) { return __uint_as_float((unsigned)(v >> 32)); }

// ---------------- device scratch (allocation-free) ----------------
__device__ float    g_w[(size_t)Bb * Tt * G2];   // 64 MB: LN'd projection
__device__ float    g_hbuf[2][Bb * Hh];          // double-buffered hidden state
__device__ unsigned g_count;                     // barrier counter (monotonic)

// ---------------- init: reset barrier state + h0 ----------------
__global__ void init_state_k(const float* __restrict__ h0) {
    int i = blockIdx.x * blockDim.x + threadIdx.x;
    if (i < Bb * Hh) g_hbuf[0][i] = h0[i & (Hh - 1)];   // broadcast h0 over batch
    if (i == 0)      g_count = 0u;
}

// ---------------- phase 1: g_w = x @ W^T  (f32x2 tiled GEMM) ----------------
// Register double-buffered: next k-tile's LDGs overlap the compute phase.
__global__ void __launch_bounds__(256) gemm_xw_k(const float* __restrict__ X,
                                                 const float* __restrict__ W) {
    __shared__ float2 As2[4][128];
    __shared__ float2 Bs2[4][66];

    int tid = threadIdx.x;
    int bx = blockIdx.x;          // n tile (32)
    int by = blockIdx.y;          // m tile (64)
    int tx = tid & 15;            // n lane
    int ty = tid >> 4;            // m lane (0..15)

    int lmA = tid >> 1;           // 0..127 (m row)
    int lkA = (tid & 1) * 4;      // k sub (0 or 4)
    int lnB = tid >> 1;
    int lkB = (tid & 1) * 4;

    const float* Xp = X + (size_t)(by * 128 + lmA) * Dd + lkA;
    const float* Wp = W + (size_t)(bx * 64 + lnB) * Dd + lkB;

    u64 acc[8][4];
#pragma unroll
    for (int i = 0; i < 8; ++i)
#pragma unroll
        for (int j = 0; j < 4; ++j) acc[i][j] = 0ull;

    int kpA = lkA >> 1;
    int kpB = lkB >> 1;

    // preload k-tile 0
    float4 xa = *(const float4*)(Xp);
    float4 wa = make_float4(0.f, 0.f, 0.f, 0.f);
    if (tid < 128) wa = *(const float4*)(Wp);

    for (int k0 = 0; k0 < Dd; k0 += 8) {
        As2[kpA][lmA]     = make_float2(xa.x, xa.y);
        As2[kpA + 1][lmA] = make_float2(xa.z, xa.w);
        if (tid < 128) {
            Bs2[kpB][lnB]     = make_float2(wa.x, wa.y);
            Bs2[kpB + 1][lnB] = make_float2(wa.z, wa.w);
        }
        __syncthreads();

        if (k0 + 8 < Dd) {
            xa = *(const float4*)(Xp + k0 + 8);
            if (tid < 128) wa = *(const float4*)(Wp + k0 + 8);
        }

#pragma unroll
        for (int p = 0; p < 4; ++p) {
            u64 a[8], b[4];
            ulonglong2 a0 = *(const ulonglong2*)&As2[p][ty * 8 + 0];
            ulonglong2 a1 = *(const ulonglong2*)&As2[p][ty * 8 + 2];
            ulonglong2 a2 = *(const ulonglong2*)&As2[p][ty * 8 + 4];
            ulonglong2 a3 = *(const ulonglong2*)&As2[p][ty * 8 + 6];
            a[0] = a0.x; a[1] = a0.y; a[2] = a1.x; a[3] = a1.y;
            a[4] = a2.x; a[5] = a2.y; a[6] = a3.x; a[7] = a3.y;
#pragma unroll
            for (int jj = 0; jj < 4; ++jj)
                b[jj] = *(const u64*)&Bs2[p][tx + 16 * jj];
#pragma unroll
            for (int i = 0; i < 8; ++i)
#pragma unroll
                for (int jj = 0; jj < 4; ++jj)
                    fma2(acc[i][jj], a[i], b[jj]);
        }
        __syncthreads();
    }
#pragma unroll
    for (int i = 0; i < 8; ++i) {
        size_t row = (size_t)(by * 128 + ty * 8 + i);
#pragma unroll
        for (int jj = 0; jj < 4; ++jj) {
            int col = bx * 64 + tx + 16 * jj;
            g_w[row * G2 + col] = lo_f(acc[i][jj]) + hi_f(acc[i][jj]);
        }
    }
}

// ---------------- phase 2: in-place rowwise LayerNorm over 2H ----------------
__global__ void __launch_bounds__(256) ln_rows_k(const float* __restrict__ gamma,
                                                 const float* __restrict__ beta) {
    int row = blockIdx.x;
    float* p = g_w + (size_t)row * G2;
    int tid = threadIdx.x;

    float4 v0 = *(const float4*)(p + tid * 4);
    float4 v1 = *(const float4*)(p + 1024 + tid * 4);
    float s  = v0.x + v0.y + v0.z + v0.w + v1.x + v1.y + v1.z + v1.w;
    float s2 = v0.x*v0.x + v0.y*v0.y + v0.z*v0.z + v0.w*v0.w
             + v1.x*v1.x + v1.y*v1.y + v1.z*v1.z + v1.w*v1.w;

#pragma unroll
    for (int o = 16; o > 0; o >>= 1) {
        s  += __shfl_xor_sync(0xFFFFFFFFu, s,  o);
        s2 += __shfl_xor_sync(0xFFFFFFFFu, s2, o);
    }
    __shared__ float rs[8], rs2[8];
    __shared__ float mean_s, inv_s;
    int wid = tid >> 5;
    if ((tid & 31) == 0) { rs[wid] = s; rs2[wid] = s2; }
    __syncthreads();
    if (tid == 0) {
        float S = 0.f, S2 = 0.f;
#pragma unroll
        for (int w = 0; w < 8; ++w) { S += rs[w]; S2 += rs2[w]; }
        float m  = S * (1.f / G2);
        float var = S2 * (1.f / G2) - m * m;
        mean_s = m;
        inv_s = rsqrtf(var + LN_EPS);
    }
    __syncthreads();
    float m = mean_s, inv = inv_s;

    float4 g0v = *(const float4*)(gamma + tid * 4);
    float4 b0v = *(const float4*)(beta  + tid * 4);
    float4 g1v = *(const float4*)(gamma + 1024 + tid * 4);
    float4 b1v = *(const float4*)(beta  + 1024 + tid * 4);
    float4 o0, o1;
    o0.x = (v0.x - m) * inv * g0v.x + b0v.x;
    o0.y = (v0.y - m) * inv * g0v.y + b0v.y;
    o0.z = (v0.z - m) * inv * g0v.z + b0v.z;
    o0.w = (v0.w - m) * inv * g0v.w + b0v.w;
    o1.x = (v1.x - m) * inv * g1v.x + b1v.x;
    o1.y = (v1.y - m) * inv * g1v.y + b1v.y;
    o1.z = (v1.z - m) * inv * g1v.z + b1v.z;
    o1.w = (v1.w - m) * inv * g1v.w + b1v.w;
    *(float4*)(p + tid * 4)        = o0;
    *(float4*)(p + 1024 + tid * 4) = o1;
}

// ---------------- phase 3: persistent recurrence ----------------
// R7 body; epilogue change only: gates reduction (256 thr, 16 conflict-free
// LDS each, unchanged) now pairs a/z via shfl_xor(8) inside the warp and the
// a-lane does the combine directly. Deletes gates[] round trip + 1 barrier.
__global__ void __launch_bounds__(512, 1) ligru_rec_k(const float* __restrict__ U,
                                                      float* __restrict__ out) {
    extern __shared__ float sm[];
    float* Us    = sm;                     // 16 * STR
    float* hs    = sm + 16 * STR;          // 16 * STR
    float* red   = hs + 16 * STR;          // 16 * RQS = 4352

    int tid = threadIdx.x;
    int bid = blockIdx.x;
    int jbase = bid * JPB;

    // Load U slice (rows 0..7 = a-rows, 8..15 = z-rows), swizzled, once.
#pragma unroll 1
    for (int pass = 0; pass < 8; ++pass) {
        int r = pass * 2 + (tid >> 8);
        int c4 = tid & 255;
        int grow = (r < 8) ? (jbase + r) : (Hh + jbase + (r - 8));
        float4 v = *(const float4*)(U + (size_t)grow * Hh + (c4 << 2));
        int col = (c4 << 2) ^ ((c4 & 8) << 1) ^ (r & 12);
        *(float4*)(Us + r * STR + col) = v;
    }

    int q   = tid >> 4;            // 0..31 : k-slice [q*32, q*32+32)
    int tbg = tid & 15;
    int tb  = tbg >> 2;            // batches tb*4 .. tb*4+3
    int tg  = tbg & 3;             // gate rows tg*4 .. tg*4+3
    int kbase = q * 32;

    int w    = tid >> 5;           // warp id (0..15): stages k [w*64, w*64+64)
    int lane = tid & 31;

    int qx   = (q & 1) << 4;       // bit5(kbase) << 4
    int hxor = qx ^ (tb << 2);     // swizzle constant for my h rows
    int uxor = qx ^ (tg << 2);     // swizzle constant for my U rows

    const float* hpc = hs + (tb * 4) * STR + kbase;
    const float* upc = Us + (tg * 4) * STR + kbase;
    int ibase = (lane < 16) ? 0 : 2;   // rows of 4x4 tile this half-warp writes
    float* redw = red + w * RQS + tb * 68 + ibase * 16 + tg * 4;

    // gates/combine role (tid < 256)
    int wb = tid >> 4;             // batch 0..15
    int wg = tid & 15;             // gate row 0..15 (wg<8 = a-row, else z-row)
    int wcol = (wg < 8) ? (jbase + wg) : (Hh + jbase + (wg - 8));
    int rbase = (wb >> 2) * 68 + (wb & 3) * 16 + (wg >> 2) * 4 + (wg & 3);
    bool is_a = (tid < 256) && (wg < 8);
    int hidx  = wb * Hh + jbase + wg;              // valid for a-lanes
    size_t outbase = (size_t)wb * (Tt * Hh) + jbase + wg;

    float hprev = 0.f;
    if (is_a) hprev = g_hbuf[0][hidx];

    __syncthreads();  // Us ready

    // preload w for t=0
    float wv = 0.f;
    if (tid < 256) wv = __ldg(g_w + (size_t)(wb * Tt + 0) * G2 + wcol);

    unsigned buf = 0;
    for (int t = 0; t < Tt; ++t) {
        // Warp-local h staging: warp w loads k [w*64, w*64+64) for all 16 b,
        // storing at swizzled columns.
        {
            const float4* hsrc4 = (const float4*)(g_hbuf[buf]);
#pragma unroll
            for (int j = 0; j < 8; ++j) {
                int idx = lane + 32 * j;      // 0..255
                int b   = idx >> 4;           // 0..15
                int f4  = idx & 15;           // 0..15
                float4 v = __ldcg(hsrc4 + b * 256 + w * 16 + f4);
                int col = (w * 64 + (f4 << 2)) ^ ((f4 & 8) << 1) ^ (b & 12);
                *(float4*)(hs + b * STR + col) = v;
            }
        }
        __syncwarp();

        // 4x4 register tile over 32 k (16 f32x2 pairs), swizzled reads
        u64 acc[4][4];
#pragma unroll
        for (int i = 0; i < 4; ++i)
#pragma unroll
            for (int j = 0; j < 4; ++j) acc[i][j] = 0ull;

#pragma unroll
        for (int kk = 0; kk < 32; kk += 4) {
            int ko_h = kk ^ hxor;
            int ko_u = kk ^ uxor;
            ulonglong2 hv[4], uv[4];
#pragma unroll
            for (int i = 0; i < 4; ++i)
                hv[i] = *(const ulonglong2*)(hpc + i * STR + ko_h);
#pragma unroll
            for (int j = 0; j < 4; ++j)
                uv[j] = *(const ulonglong2*)(upc + j * STR + ko_u);
#pragma unroll
            for (int i = 0; i < 4; ++i)
#pragma unroll
                for (int j = 0; j < 4; ++j) {
                    fma2(acc[i][j], hv[i].x, uv[j].x);
                    fma2(acc[i][j], hv[i].y, uv[j].y);
                }
        }

        // fold f32x2 halves, pre-reduce q-pair across lane^16, store 2 rows
        float c[4][4];
#pragma unroll
        for (int i = 0; i < 4; ++i)
#pragma unroll
            for (int j = 0; j < 4; ++j) {
                float v = lo_f(acc[i][j]) + hi_f(acc[i][j]);
                v += __shfl_xor_sync(0xFFFFFFFFu, v, 16);
                c[i][j] = v;
            }
#pragma unroll
        for (int ii = 0; ii < 2; ++ii) {
            int i = ibase + ii;
            *(float4*)(redw + ii * 16) = make_float4(c[i][0], c[i][1], c[i][2], c[i][3]);
        }
        __syncthreads();   // red ready

        // Merged gates + combine: 256 threads reduce (16 conflict-free LDS),
        // then a-lanes fetch the z-gate from lane^8 and update h.
        float hn = 0.f;
        if (tid < 256) {
            float s0 = 0.f, s1 = 0.f, s2 = 0.f, s3 = 0.f;
#pragma unroll
            for (int q2 = 0; q2 < 16; q2 += 4) {
                s0 += red[rbase + (q2 + 0) * RQS];
                s1 += red[rbase + (q2 + 1) * RQS];
                s2 += red[rbase + (q2 + 2) * RQS];
                s3 += red[rbase + (q2 + 3) * RQS];
            }
            float gsum = wv + (s0 + s1) + (s2 + s3);
            float other = __shfl_xor_sync(0xFFFFFFFFu, gsum, 8);
            if (wg < 8) {                      // a-lane: gsum=a, other=z-gate
                float z = 1.f / (1.f + __expf(-other));
                hn = z * hprev + (1.f - z) * fmaxf(gsum, 0.f);
                hprev = hn;
                g_hbuf[buf ^ 1u][hidx] = hn;
            }
        }
        __syncthreads();   // h stores ordered before the release below

        bool last = (t + 1 == Tt);
        // Release first; overlap out-store + next-w prefetch with the poll.
        if (!last && tid == 0) red_rel_add(&g_count, 1u);
        if (is_a)
            out[outbase + (size_t)t * Hh] = hn;
        float wv_n = 0.f;
        if (!last && tid < 256)
            wv_n = __ldg(g_w + (size_t)(wb * Tt + (t + 1)) * G2 + wcol);
        if (!last && tid == 0) {
            unsigned target = (unsigned)(t + 1) * NB;
            while (ld_acq(&g_count) < target) { }
        }
        __syncthreads();

        wv = wv_n;
        buf ^= 1u;
    }
}

// ---------------- launch ----------------
extern "C" void kernel_launch(void* const* d_in, const int* in_sizes, int n_in,
                              void* d_out, int out_size) {
    const float* x     = (const float*)d_in[0];   // [16,512,512]
    const float* W_w   = (const float*)d_in[1];   // [2048,512]
    const float* U_w   = (const float*)d_in[2];   // [2048,1024]
    const float* gamma = (const float*)d_in[3];   // [2048]
    const float* beta  = (const float*)d_in[4];   // [2048]
    const float* h0    = (const float*)d_in[5];   // [1,1024]
    float* out = (float*)d_out;                   // [16,512,1024]

    const int smem_rec = (2 * 16 * STR + 16 * RQS + 16) * (int)sizeof(float);
    cudaFuncSetAttribute(ligru_rec_k, cudaFuncAttributeMaxDynamicSharedMemorySize,
                         smem_rec);

    init_state_k<<<64, 256>>>(h0);

    dim3 gg(G2 / 64, (Bb * Tt) / 128);
    gemm_xw_k<<<gg, 256>>>(x, W_w);

    ln_rows_k<<<Bb * Tt, 256>>>(gamma, beta);

    ligru_rec_k<<<NB, 512, smem_rec>>>(U_w, out);
}